// round 14
// baseline (speedup 1.0000x reference)
#include <cuda_runtime.h>
#include <cuda_fp16.h>
#include <cstdint>

// Problem: B=128, L_IM=50, L_S=40, D=1024
// im = im_set[:,1:,:]  -> il = im_len-1 valid rows (9..49)
// s  = s_seq[:,1:-2,:] -> sl = s_len-3  valid rows (7..37)
// Batches are bin-packed (whole) into dense GEMM tiles:
//   M: ceil(il/16) x 16-row fragments, 8 per 128-row tile  (<= 64 tiles)
//   N: ceil(sl/8)  x 8-col blocks,   40 per 320-col tile  (<= 16 tiles)
// Packing is computed in CLOSED FORM per thread (no serial walk); result is
// bit-identical to first-fit over class-descending, index-ascending order.
#define NBATCH 128
#define DDIM   1024
#define AROWS  64
#define SROWS  40

__device__ __align__(1024) __half g_A[(size_t)NBATCH * AROWS * DDIM];  // 16 MB
__device__ __align__(1024) __half g_S[(size_t)NBATCH * SROWS * DDIM];  // 10 MB

// ---- packing plan ----
__device__ int g_TM, g_TN;
__device__ int g_fB[64 * 8],  g_fR[64 * 8];    // M tile fragment -> batch, row base
__device__ int g_mN[64], g_mB[64 * 8], g_mRS[64 * 8], g_mIL[64 * 8];
__device__ int g_bJ[16 * 40], g_bW[16 * 40];   // N tile block -> batch, w base
__device__ int g_nN[16], g_nB[16 * 40], g_nCS[16 * 40], g_nSL[16 * 40];

// ---------------- helpers ----------------
__device__ __forceinline__ uint32_t smem_u32(const void* p) {
    uint32_t a;
    asm("{ .reg .u64 t; cvta.to.shared.u64 t, %1; cvt.u32.u64 %0, t; }" : "=r"(a) : "l"(p));
    return a;
}

#define CP_ASYNC16Z(dst, src, sz) \
    asm volatile("cp.async.cg.shared.global [%0], [%1], 16, %2;" \
                 :: "r"(dst), "l"(src), "r"(sz))
#define CP_COMMIT() asm volatile("cp.async.commit_group;" ::: "memory")
#define CP_WAIT1()  asm volatile("cp.async.wait_group 1;" ::: "memory")

#define LDSM4(r, addr) \
    asm volatile("ldmatrix.sync.aligned.m8n8.x4.shared.b16 {%0,%1,%2,%3}, [%4];" \
                 : "=r"((r)[0]), "=r"((r)[1]), "=r"((r)[2]), "=r"((r)[3]) : "r"(addr))

#define MMA16816(c, a, b0, b1) \
    asm volatile("mma.sync.aligned.m16n8k16.row.col.f32.f16.f16.f32 " \
                 "{%0,%1,%2,%3},{%4,%5,%6,%7},{%8,%9},{%0,%1,%2,%3};" \
                 : "+f"((c)[0]), "+f"((c)[1]), "+f"((c)[2]), "+f"((c)[3]) \
                 : "r"((a)[0]), "r"((a)[1]), "r"((a)[2]), "r"((a)[3]), "r"(b0), "r"(b1))

// Closed-form first-fit over classes DESCENDING (cmax..1), rank r within class.
// cap = tile capacity (fragments). Returns this item's (tile, off, slot) and
// final (t0,u0,s0) state -> tile count. Identical to the serial walk.
struct PackPos { int tile, off, slot, ntiles; };
__device__ __forceinline__ PackPos pack_pos(int myClass, int myRank,
                                            const int* cnt, int cmax, int cap) {
    int t0 = 0, u0 = 0, s0 = 0;
    PackPos p; p.tile = 0; p.off = 0; p.slot = 0;
    for (int c = cmax; c >= 1; c--) {
        int n  = cnt[c];
        int k0 = (cap - u0) / c;        // items fitting in current tile
        int kc = cap / c;               // items per fresh tile
        if (c == myClass) {
            if (myRank < k0) { p.tile = t0; p.off = u0 + myRank * c; p.slot = s0 + myRank; }
            else {
                int rp = myRank - k0;
                p.tile = t0 + 1 + rp / kc;
                p.off  = (rp % kc) * c;
                p.slot = rp % kc;
            }
        }
        if (n > 0) {
            if (n <= k0) { u0 += n * c; s0 += n; }
            else {
                int rp   = n - k0;
                int full = (rp - 1) / kc;
                int last = (rp - 1) % kc + 1;
                t0 += 1 + full;
                u0 = last * c;
                s0 = last;
            }
        }
    }
    p.ntiles = t0 + 1;
    return p;
}

// ------------- planner: fully parallel (no serial walk) -------------
__global__ void plan_kernel(const int* __restrict__ im_len, const int* __restrict__ s_len) {
    __shared__ int wcM[4][5], wcN[4][6];           // [warp][class]
    __shared__ int s_fB[64 * 8], s_fR[64 * 8];
    __shared__ int s_mN[64], s_mB[64 * 8], s_mRS[64 * 8], s_mIL[64 * 8];
    __shared__ int s_bJ[16 * 40], s_bW[16 * 40];
    __shared__ int s_nN[16], s_nB[16 * 40], s_nCS[16 * 40], s_nSL[16 * 40];
    const int t = threadIdx.x, w = t >> 5, ln = t & 31;
    const uint32_t lmask = (1u << ln) - 1u;

    int vI = im_len[t] - 1;  vI = vI < 1 ? 1 : (vI > 49 ? 49 : vI);
    int vS = s_len[t] - 3;   vS = vS < 1 ? 1 : (vS > 37 ? 37 : vS);
    const int frM = (vI + 15) >> 4;   // class 1..4
    const int frN = (vS + 7) >> 3;    // class 1..5

    int rkM = 0, rkN = 0;             // rank within class, within warp
#pragma unroll
    for (int c = 1; c <= 4; c++) {
        uint32_t b = __ballot_sync(0xffffffffu, frM == c);
        if (frM == c) rkM = __popc(b & lmask);
        if (ln == 0) wcM[w][c] = __popc(b);
    }
#pragma unroll
    for (int c = 1; c <= 5; c++) {
        uint32_t b = __ballot_sync(0xffffffffu, frN == c);
        if (frN == c) rkN = __popc(b & lmask);
        if (ln == 0) wcN[w][c] = __popc(b);
    }
    for (int k = t; k < 64 * 8; k += 128)  { s_fB[k] = -1; s_fR[k] = 0; s_mB[k] = 0; s_mRS[k] = 0; s_mIL[k] = 1; }
    for (int k = t; k < 16 * 40; k += 128) { s_bJ[k] = -1; s_bW[k] = 0; s_nB[k] = 0; s_nCS[k] = 0; s_nSL[k] = 1; }
    if (t < 64) s_mN[t] = 0;
    if (t < 16) s_nN[t] = 0;
    __syncthreads();

    // global class counts + global rank within class
    int cntM[5], cntN[6];
#pragma unroll
    for (int c = 1; c <= 4; c++) cntM[c] = wcM[0][c] + wcM[1][c] + wcM[2][c] + wcM[3][c];
#pragma unroll
    for (int c = 1; c <= 5; c++) cntN[c] = wcN[0][c] + wcN[1][c] + wcN[2][c] + wcN[3][c];
    for (int ww = 0; ww < 4; ww++) {
        if (ww < w) { rkM += wcM[ww][frM]; rkN += wcN[ww][frN]; }
    }

    // closed-form position (all threads, pure registers)
    PackPos pM = pack_pos(frM, rkM, cntM, 4, 8);
    PackPos pN = pack_pos(frN, rkN, cntN, 5, 40);

    // write plan entries (each thread owns its batch)
    s_mB[pM.tile * 8 + pM.slot]  = t;
    s_mRS[pM.tile * 8 + pM.slot] = pM.off * 16;
    s_mIL[pM.tile * 8 + pM.slot] = vI;
    atomicAdd(&s_mN[pM.tile], 1);
    for (int q = 0; q < frM; q++) {
        s_fB[pM.tile * 8 + pM.off + q] = t;
        s_fR[pM.tile * 8 + pM.off + q] = q * 16;
    }
    s_nB[pN.tile * 40 + pN.slot]  = t;
    s_nCS[pN.tile * 40 + pN.slot] = pN.off * 8;
    s_nSL[pN.tile * 40 + pN.slot] = vS;
    atomicAdd(&s_nN[pN.tile], 1);
    for (int q = 0; q < frN; q++) {
        s_bJ[pN.tile * 40 + pN.off + q] = t;
        s_bW[pN.tile * 40 + pN.off + q] = q * 8;
    }
    __syncthreads();

    for (int k = t; k < 64 * 8; k += 128) {
        g_fB[k] = s_fB[k];  g_fR[k] = s_fR[k];
        g_mB[k] = s_mB[k];  g_mRS[k] = s_mRS[k];  g_mIL[k] = s_mIL[k];
    }
    for (int k = t; k < 16 * 40; k += 128) {
        g_bJ[k] = s_bJ[k];  g_bW[k] = s_bW[k];
        g_nB[k] = s_nB[k];  g_nCS[k] = s_nCS[k];  g_nSL[k] = s_nSL[k];
    }
    if (t < 64) g_mN[t] = s_mN[t];
    if (t < 16) g_nN[t] = s_nN[t];
    if (t == 0) { g_TM = pM.ntiles; g_TN = pN.ntiles; }
}

// ------------- merged conversion: fp32 -> fp16, valid rows only -------------
__global__ void conv_kernel(const float* __restrict__ im, const float* __restrict__ s,
                            const int* __restrict__ im_len, const int* __restrict__ s_len) {
    int b = blockIdx.x;
    if (b < 4096) {                                     // A path
        int u = b * 256 + threadIdx.x;                  // < 128*64*128
        int i  = u >> 13;
        int r  = (u >> 7) & 63;
        int d0 = (u & 127) << 3;
        int L = im_len[i] - 1;
        if (r >= L || r >= 49) return;
        const float* src = im + ((size_t)i * 50 + r + 1) * DDIM + d0;
        float4 f0 = ((const float4*)src)[0];
        float4 f1 = ((const float4*)src)[1];
        union { uint4 v; __half2 h[4]; } pk;
        pk.h[0] = __float22half2_rn(make_float2(f0.x, f0.y));
        pk.h[1] = __float22half2_rn(make_float2(f0.z, f0.w));
        pk.h[2] = __float22half2_rn(make_float2(f1.x, f1.y));
        pk.h[3] = __float22half2_rn(make_float2(f1.z, f1.w));
        *((uint4*)(g_A + ((size_t)i * AROWS + r) * DDIM + d0)) = pk.v;
    } else {                                            // S path
        int u = (b - 4096) * 256 + threadIdx.x;         // < 128*40*128
        int i   = u / (SROWS * 128);
        int rem = u - i * (SROWS * 128);
        int r  = rem >> 7;
        int d0 = (rem & 127) << 3;
        int L = s_len[i] - 3;
        if (r >= L || r >= 37) return;
        const float* src = s + ((size_t)i * 40 + r + 1) * DDIM + d0;
        float4 f0 = ((const float4*)src)[0];
        float4 f1 = ((const float4*)src)[1];
        union { uint4 v; __half2 h[4]; } pk;
        pk.h[0] = __float22half2_rn(make_float2(f0.x, f0.y));
        pk.h[1] = __float22half2_rn(make_float2(f0.z, f0.w));
        pk.h[2] = __float22half2_rn(make_float2(f1.x, f1.y));
        pk.h[3] = __float22half2_rn(make_float2(f1.z, f1.w));
        *((uint4*)(g_S + ((size_t)i * SROWS + r) * DDIM + d0)) = pk.v;
    }
}

// ------------- dense packed GEMM + per-pair masked max/sum epilogue -------------
// CTA: 512 threads, tile M=128 x N=320, K=1024 in 16 chunks of 64.
// Warp grid 4(m) x 4(n): warp tile 32 x 80. ONE barrier per k-chunk.
#define PITCH     144
#define ASTAGE    18432              // 128*144
#define STAGE_SZ  64512              // ASTAGE + 320*144
#define CPITCH    326                // even -> float2-aligned; 326*4 % 128 = 24
#define SMEM_BYTES 197632            // C (128*CPITCH*4) + RM (128*40*4) + CM (8*320*4)

__global__ void __launch_bounds__(512, 1) align_gemm_kernel(
        const int* __restrict__ im_len, const int* __restrict__ s_len,
        float* __restrict__ out) {
    const int jb = blockIdx.x;       // N tile
    const int ib = blockIdx.y;       // M tile
    if (ib >= g_TM || jb >= g_TN) return;

    extern __shared__ __align__(16) char smem[];
    const int tid  = threadIdx.x;
    const int lane = tid & 31;
    const int wid  = tid >> 5;
    const int wm   = wid & 3;        // M offset wm*32
    const int wn   = wid >> 2;       // N offset wn*80
    const uint32_t sbase = smem_u32(smem) + 128;

    // ---- per-thread load setup (advance src by 128B per kt) ----
    const char* srcA[2]; uint32_t dstA[2], szA[2];
#pragma unroll
    for (int q = 0; q < 2; q++) {
        int idx = tid + q * 512, row = idx >> 3, cc = idx & 7;
        int f = row >> 4;
        int b = g_fB[ib * 8 + f];
        int r = g_fR[ib * 8 + f] + (row & 15);
        int il = (b >= 0) ? (__ldg(&im_len[b]) - 1) : 0;
        szA[q] = (b >= 0 && r < il) ? 16u : 0u;
        int bs = b < 0 ? 0 : b;
        srcA[q] = (const char*)(g_A + ((size_t)bs * AROWS + r) * DDIM) + cc * 16;
        dstA[q] = sbase + row * PITCH + cc * 16;
    }
    const char* srcB[5]; uint32_t dstB[5], szB[5];
#pragma unroll
    for (int q = 0; q < 5; q++) {
        int idx = tid + q * 512, row = idx >> 3, cc = idx & 7;
        int blk = row >> 3;
        int j = g_bJ[jb * 40 + blk];
        int w = g_bW[jb * 40 + blk] + (row & 7);
        int sl = (j >= 0) ? (__ldg(&s_len[j]) - 3) : 0;
        szB[q] = (j >= 0 && w < sl) ? 16u : 0u;
        int js = j < 0 ? 0 : j;
        srcB[q] = (const char*)(g_S + ((size_t)js * SROWS + w) * DDIM) + cc * 16;
        dstB[q] = sbase + ASTAGE + row * PITCH + cc * 16;
    }

    // ldmatrix lane addresses
    const int quad = lane >> 3, r8 = lane & 7;
    const uint32_t a_lane = (uint32_t)((wm * 32 + (quad & 1) * 8 + r8) * PITCH
                                       + (quad >> 1) * 16);
    const uint32_t b_lane = (uint32_t)(ASTAGE
                                       + (wn * 80 + (quad >> 1) * 8 + r8) * PITCH
                                       + (quad & 1) * 16);

    float c[2][10][4];
#pragma unroll
    for (int mt = 0; mt < 2; mt++)
#pragma unroll
        for (int nt = 0; nt < 10; nt++)
#pragma unroll
            for (int q = 0; q < 4; q++) c[mt][nt][q] = 0.0f;

    // ---- prologue: 2 stages in flight ----
#pragma unroll
    for (int p = 0; p < 2; p++) {
        uint32_t so = (uint32_t)(p * STAGE_SZ), ko = (uint32_t)(p * 128);
#pragma unroll
        for (int q = 0; q < 2; q++) CP_ASYNC16Z(dstA[q] + so, srcA[q] + ko, szA[q]);
#pragma unroll
        for (int q = 0; q < 5; q++) CP_ASYNC16Z(dstB[q] + so, srcB[q] + ko, szB[q]);
        CP_COMMIT();
    }

    int stg = 0, stg_load = 2;
#pragma unroll 1
    for (int kt = 0; kt < 16; kt++) {
        CP_WAIT1();            // loads for kt complete (only kt+1's group may pend)
        __syncthreads();       // data visible; stage (kt-1)%3 == (kt+2)%3 consumer-free

        if (kt + 2 < 16) {     // prefetch kt+2 BEFORE compute -> overlaps this kt
            uint32_t so = (uint32_t)(stg_load * STAGE_SZ), ko = (uint32_t)((kt + 2) * 128);
#pragma unroll
            for (int q = 0; q < 2; q++) CP_ASYNC16Z(dstA[q] + so, srcA[q] + ko, szA[q]);
#pragma unroll
            for (int q = 0; q < 5; q++) CP_ASYNC16Z(dstB[q] + so, srcB[q] + ko, szB[q]);
        }
        CP_COMMIT();           // empty commits at tail keep wait_group accounting
        stg_load = (stg_load + 1 == 3) ? 0 : stg_load + 1;

        const uint32_t stga = sbase + stg * STAGE_SZ;
#pragma unroll
        for (int step = 0; step < 4; step++) {
            uint32_t areg[2][4], breg[5][4];
#pragma unroll
            for (int mt = 0; mt < 2; mt++)
                LDSM4(areg[mt], stga + a_lane + mt * 16 * PITCH + step * 32);
#pragma unroll
            for (int nn = 0; nn < 5; nn++)
                LDSM4(breg[nn], stga + b_lane + nn * 16 * PITCH + step * 32);
#pragma unroll
            for (int mt = 0; mt < 2; mt++)
#pragma unroll
                for (int nt = 0; nt < 10; nt++)
                    MMA16816(c[mt][nt], areg[mt], breg[nt >> 1][(nt & 1) * 2],
                             breg[nt >> 1][(nt & 1) * 2 + 1]);
        }
        stg = (stg + 1 == 3) ? 0 : stg + 1;
    }
    __syncthreads();       // compute done; smem reused for C

    // ---- store C tile to smem: [128][CPITCH] floats ----
    float* C  = (float*)smem;
    float* RM = (float*)(smem + 128 * CPITCH * 4);   // [128][40] row maxes
    float* CM = RM + 128 * 40;                       // [8][320] col maxes
#pragma unroll
    for (int mt = 0; mt < 2; mt++)
#pragma unroll
        for (int nt = 0; nt < 10; nt++) {
            int row = wm * 32 + mt * 16 + (lane >> 2);
            int col = wn * 80 + nt * 8 + (lane & 3) * 2;
            *(float2*)&C[row * CPITCH + col]       = make_float2(c[mt][nt][0], c[mt][nt][1]);
            *(float2*)&C[(row + 8) * CPITCH + col] = make_float2(c[mt][nt][2], c[mt][nt][3]);
        }
    __syncthreads();

    const int nmb = g_mN[ib], njb = g_nN[jb];

    // ---- row part: per row, per j-batch: max over w<sl (+0 iff sl<37) ----
    if (tid < 128) {
        const float* Cr = &C[tid * CPITCH];
        for (int js = 0; js < njb; js++) {
            int cs = g_nCS[jb * 40 + js], sl = g_nSL[jb * 40 + js];
            float m = Cr[cs];
            for (int w = 1; w < sl; w++) m = fmaxf(m, Cr[cs + w]);
            if (sl < 37) m = fmaxf(m, 0.0f);
            RM[tid * 40 + js] = m;
        }
    }
    // ---- col part: per col, per m-batch: max over r<il (+0 iff il<49) ----
    if (tid < 320) {
        for (int ms = 0; ms < nmb; ms++) {
            int rs = g_mRS[ib * 8 + ms], il = g_mIL[ib * 8 + ms];
            float m = C[rs * CPITCH + tid];
            for (int r = 1; r < il; r++) m = fmaxf(m, C[(rs + r) * CPITCH + tid]);
            if (il < 49) m = fmaxf(m, 0.0f);
            CM[ms * 320 + tid] = m;
        }
    }
    __syncthreads();

    // ---- per-pair reduction & output ----
    if (tid < nmb * njb) {
        int ms = tid / njb, js = tid - ms * njb;
        int rs = g_mRS[ib * 8 + ms], il = g_mIL[ib * 8 + ms];
        int cs = g_nCS[jb * 40 + js], sl = g_nSL[jb * 40 + js];
        float sum = 0.0f;
        for (int r = 0; r < il; r++) sum += RM[(rs + r) * 40 + js];
        for (int w = 0; w < sl; w++) sum += CM[ms * 320 + cs + w];
        out[g_mB[ib * 8 + ms] * NBATCH + g_nB[jb * 40 + js]] = sum;
    }
}

extern "C" void kernel_launch(void* const* d_in, const int* in_sizes, int n_in,
                              void* d_out, int out_size) {
    (void)in_sizes; (void)n_in; (void)out_size;
    const float* im   = (const float*)d_in[0];
    const float* s    = (const float*)d_in[1];
    const int* im_len = (const int*)d_in[2];
    const int* s_len  = (const int*)d_in[3];
    float* out = (float*)d_out;

    plan_kernel<<<1, 128>>>(im_len, s_len);
    conv_kernel<<<6656, 256>>>(im, s, im_len, s_len);

    cudaFuncSetAttribute(align_gemm_kernel,
                         cudaFuncAttributeMaxDynamicSharedMemorySize, SMEM_BYTES);
    dim3 grid(16, 64);
    align_gemm_kernel<<<grid, 512, SMEM_BYTES>>>(im_len, s_len, out);
}

// round 15
// speedup vs baseline: 1.2359x; 1.2359x over previous
#include <cuda_runtime.h>
#include <cuda_fp16.h>
#include <cstdint>

// Problem: B=128, L_IM=50, L_S=40, D=1024
// im = im_set[:,1:,:]  -> il = im_len-1 valid rows (9..49)
// s  = s_seq[:,1:-2,:] -> sl = s_len-3  valid rows (7..37)
// Batches bin-packed (whole) into dense GEMM tiles:
//   M: ceil(il/16) 16-row fragments, 8 per 128-row tile   (<= 64 tiles)
//   N: ceil(sl/8)  8-col blocks,    20 per 160-col tile   (<= 40 tiles)
// Packing computed in closed form (no serial walk); pad rows/cols are exact
// zeros via cp.async zfill. GEMM: 256-thr CTAs, 2 CTAs/SM for barrier overlap.
#define NBATCH 128
#define DDIM   1024
#define AROWS  64
#define SROWS  40
#define NCAP   20        // N blocks per tile
#define TNMAX  40

__device__ __align__(1024) __half g_A[(size_t)NBATCH * AROWS * DDIM];  // 16 MB
__device__ __align__(1024) __half g_S[(size_t)NBATCH * SROWS * DDIM];  // 10 MB

// ---- packing plan ----
__device__ int g_TM, g_TN;
__device__ int g_fB[64 * 8],  g_fR[64 * 8];          // M fragment -> batch, row base
__device__ int g_mN[64], g_mB[64 * 8], g_mRS[64 * 8], g_mIL[64 * 8];
__device__ int g_bJ[TNMAX * NCAP], g_bW[TNMAX * NCAP];   // N block -> batch, w base
__device__ int g_nN[TNMAX], g_nB[TNMAX * NCAP], g_nCS[TNMAX * NCAP], g_nSL[TNMAX * NCAP];

// ---------------- helpers ----------------
__device__ __forceinline__ uint32_t smem_u32(const void* p) {
    uint32_t a;
    asm("{ .reg .u64 t; cvta.to.shared.u64 t, %1; cvt.u32.u64 %0, t; }" : "=r"(a) : "l"(p));
    return a;
}

#define CP_ASYNC16Z(dst, src, sz) \
    asm volatile("cp.async.cg.shared.global [%0], [%1], 16, %2;" \
                 :: "r"(dst), "l"(src), "r"(sz))
#define CP_COMMIT() asm volatile("cp.async.commit_group;" ::: "memory")
#define CP_WAIT0()  asm volatile("cp.async.wait_group 0;" ::: "memory")

#define LDSM4(r, addr) \
    asm volatile("ldmatrix.sync.aligned.m8n8.x4.shared.b16 {%0,%1,%2,%3}, [%4];" \
                 : "=r"((r)[0]), "=r"((r)[1]), "=r"((r)[2]), "=r"((r)[3]) : "r"(addr))

#define MMA16816(c, a, b0, b1) \
    asm volatile("mma.sync.aligned.m16n8k16.row.col.f32.f16.f16.f32 " \
                 "{%0,%1,%2,%3},{%4,%5,%6,%7},{%8,%9},{%0,%1,%2,%3};" \
                 : "+f"((c)[0]), "+f"((c)[1]), "+f"((c)[2]), "+f"((c)[3]) \
                 : "r"((a)[0]), "r"((a)[1]), "r"((a)[2]), "r"((a)[3]), "r"(b0), "r"(b1))

// Closed-form first-fit over classes DESCENDING, rank within class.
struct PackPos { int tile, off, slot, ntiles; };
__device__ __forceinline__ PackPos pack_pos(int myClass, int myRank,
                                            const int* cnt, int cmax, int cap) {
    int t0 = 0, u0 = 0, s0 = 0;
    PackPos p; p.tile = 0; p.off = 0; p.slot = 0;
    for (int c = cmax; c >= 1; c--) {
        int n  = cnt[c];
        int k0 = (cap - u0) / c;
        int kc = cap / c;
        if (c == myClass) {
            if (myRank < k0) { p.tile = t0; p.off = u0 + myRank * c; p.slot = s0 + myRank; }
            else {
                int rp = myRank - k0;
                p.tile = t0 + 1 + rp / kc;
                p.off  = (rp % kc) * c;
                p.slot = rp % kc;
            }
        }
        if (n > 0) {
            if (n <= k0) { u0 += n * c; s0 += n; }
            else {
                int rp   = n - k0;
                int full = (rp - 1) / kc;
                int last = (rp - 1) % kc + 1;
                t0 += 1 + full;
                u0 = last * c;
                s0 = last;
            }
        }
    }
    p.ntiles = t0 + 1;
    return p;
}

// ------------- merged conversion + planning -------------
// Blocks 0..6655: fp32->fp16 conversion (valid rows only).
// Block 6656: closed-form packing plan (threads 0..127).
__global__ void conv_plan_kernel(const float* __restrict__ im, const float* __restrict__ s,
                                 const int* __restrict__ im_len, const int* __restrict__ s_len) {
    __shared__ int wcM[4][5], wcN[4][6];
    __shared__ int s_fB[64 * 8], s_fR[64 * 8];
    __shared__ int s_mN[64], s_mB[64 * 8], s_mRS[64 * 8], s_mIL[64 * 8];
    __shared__ int s_bJ[TNMAX * NCAP], s_bW[TNMAX * NCAP];
    __shared__ int s_nN[TNMAX], s_nB[TNMAX * NCAP], s_nCS[TNMAX * NCAP], s_nSL[TNMAX * NCAP];

    int b = blockIdx.x;
    if (b < 4096) {                                     // A path
        int u = b * 256 + threadIdx.x;
        int i  = u >> 13;
        int r  = (u >> 7) & 63;
        int d0 = (u & 127) << 3;
        int L = im_len[i] - 1;
        if (r >= L || r >= 49) return;
        const float* src = im + ((size_t)i * 50 + r + 1) * DDIM + d0;
        float4 f0 = ((const float4*)src)[0];
        float4 f1 = ((const float4*)src)[1];
        union { uint4 v; __half2 h[4]; } pk;
        pk.h[0] = __float22half2_rn(make_float2(f0.x, f0.y));
        pk.h[1] = __float22half2_rn(make_float2(f0.z, f0.w));
        pk.h[2] = __float22half2_rn(make_float2(f1.x, f1.y));
        pk.h[3] = __float22half2_rn(make_float2(f1.z, f1.w));
        *((uint4*)(g_A + ((size_t)i * AROWS + r) * DDIM + d0)) = pk.v;
    } else if (b < 6656) {                              // S path
        int u = (b - 4096) * 256 + threadIdx.x;
        int i   = u / (SROWS * 128);
        int rem = u - i * (SROWS * 128);
        int r  = rem >> 7;
        int d0 = (rem & 127) << 3;
        int L = s_len[i] - 3;
        if (r >= L || r >= 37) return;
        const float* src = s + ((size_t)i * 40 + r + 1) * DDIM + d0;
        float4 f0 = ((const float4*)src)[0];
        float4 f1 = ((const float4*)src)[1];
        union { uint4 v; __half2 h[4]; } pk;
        pk.h[0] = __float22half2_rn(make_float2(f0.x, f0.y));
        pk.h[1] = __float22half2_rn(make_float2(f0.z, f0.w));
        pk.h[2] = __float22half2_rn(make_float2(f1.x, f1.y));
        pk.h[3] = __float22half2_rn(make_float2(f1.z, f1.w));
        *((uint4*)(g_S + ((size_t)i * SROWS + r) * DDIM + d0)) = pk.v;
    } else {                                            // planning block
        const int t = threadIdx.x;
        if (t >= 128) return;
        const int w = t >> 5, ln = t & 31;
        const uint32_t lmask = (1u << ln) - 1u;

        int vI = im_len[t] - 1;  vI = vI < 1 ? 1 : (vI > 49 ? 49 : vI);
        int vS = s_len[t] - 3;   vS = vS < 1 ? 1 : (vS > 37 ? 37 : vS);
        const int frM = (vI + 15) >> 4;   // class 1..4
        const int frN = (vS + 7) >> 3;    // class 1..5

        int rkM = 0, rkN = 0;
#pragma unroll
        for (int c = 1; c <= 4; c++) {
            uint32_t bb = __ballot_sync(0xffffffffu, frM == c);
            if (frM == c) rkM = __popc(bb & lmask);
            if (ln == 0) wcM[w][c] = __popc(bb);
        }
#pragma unroll
        for (int c = 1; c <= 5; c++) {
            uint32_t bb = __ballot_sync(0xffffffffu, frN == c);
            if (frN == c) rkN = __popc(bb & lmask);
            if (ln == 0) wcN[w][c] = __popc(bb);
        }
        for (int k = t; k < 64 * 8; k += 128)
            { s_fB[k] = -1; s_fR[k] = 0; s_mB[k] = 0; s_mRS[k] = 0; s_mIL[k] = 1; }
        for (int k = t; k < TNMAX * NCAP; k += 128)
            { s_bJ[k] = -1; s_bW[k] = 0; s_nB[k] = 0; s_nCS[k] = 0; s_nSL[k] = 1; }
        if (t < 64) s_mN[t] = 0;
        if (t < TNMAX) s_nN[t] = 0;
        __syncwarp(); __syncthreads();

        int cntM[5], cntN[6];
#pragma unroll
        for (int c = 1; c <= 4; c++) cntM[c] = wcM[0][c] + wcM[1][c] + wcM[2][c] + wcM[3][c];
#pragma unroll
        for (int c = 1; c <= 5; c++) cntN[c] = wcN[0][c] + wcN[1][c] + wcN[2][c] + wcN[3][c];
        for (int ww = 0; ww < 4; ww++)
            if (ww < w) { rkM += wcM[ww][frM]; rkN += wcN[ww][frN]; }

        PackPos pM = pack_pos(frM, rkM, cntM, 4, 8);
        PackPos pN = pack_pos(frN, rkN, cntN, 5, NCAP);

        s_mB[pM.tile * 8 + pM.slot]  = t;
        s_mRS[pM.tile * 8 + pM.slot] = pM.off * 16;
        s_mIL[pM.tile * 8 + pM.slot] = vI;
        atomicAdd(&s_mN[pM.tile], 1);
        for (int q = 0; q < frM; q++) {
            s_fB[pM.tile * 8 + pM.off + q] = t;
            s_fR[pM.tile * 8 + pM.off + q] = q * 16;
        }
        s_nB[pN.tile * NCAP + pN.slot]  = t;
        s_nCS[pN.tile * NCAP + pN.slot] = pN.off * 8;
        s_nSL[pN.tile * NCAP + pN.slot] = vS;
        atomicAdd(&s_nN[pN.tile], 1);
        for (int q = 0; q < frN; q++) {
            s_bJ[pN.tile * NCAP + pN.off + q] = t;
            s_bW[pN.tile * NCAP + pN.off + q] = q * 8;
        }
        __syncthreads();

        for (int k = t; k < 64 * 8; k += 128) {
            g_fB[k] = s_fB[k];  g_fR[k] = s_fR[k];
            g_mB[k] = s_mB[k];  g_mRS[k] = s_mRS[k];  g_mIL[k] = s_mIL[k];
        }
        for (int k = t; k < TNMAX * NCAP; k += 128) {
            g_bJ[k] = s_bJ[k];  g_bW[k] = s_bW[k];
            g_nB[k] = s_nB[k];  g_nCS[k] = s_nCS[k];  g_nSL[k] = s_nSL[k];
        }
        if (t < 64) g_mN[t] = s_mN[t];
        if (t < TNMAX) g_nN[t] = s_nN[t];
        if (t == 0) { g_TM = pM.ntiles; g_TN = pN.ntiles; }
    }
}

// ------------- dense packed GEMM + per-pair masked max/sum epilogue -------------
// CTA: 256 threads, tile M=128 x N=160, K=1024 in 16 chunks of 64.
// Warp grid 4(m) x 2(n): warp tile 32 x 80. 2 stages, 1 barrier per kt.
// 2 CTAs/SM: independent CTAs fill each other's barrier/CP_WAIT bubbles.
#define PITCH     144
#define ASTAGE    18432              // 128*144
#define STAGE_SZ  41472              // ASTAGE + 160*144
#define CPITCH    166                // even; 166*4 % 128 = 24 -> conflict-free rows
#define SMEM_BYTES 100352            // max(2*STAGE_SZ, C+RM+CM)

__global__ void __launch_bounds__(256, 2) align_gemm_kernel(
        const int* __restrict__ im_len, const int* __restrict__ s_len,
        float* __restrict__ out) {
    const int jb = blockIdx.x;       // N tile (0..TNMAX-1)
    const int ib = blockIdx.y;       // M tile (0..63)
    if (ib >= g_TM || jb >= g_TN) return;

    extern __shared__ __align__(16) char smem[];
    const int tid  = threadIdx.x;
    const int lane = tid & 31;
    const int wid  = tid >> 5;
    const int wm   = wid & 3;        // M offset wm*32
    const int wn   = wid >> 2;       // N offset wn*80 (0..1)
    const uint32_t sbase = smem_u32(smem);

    // ---- per-thread load setup (advance src by 128B per kt) ----
    const char* srcA[4]; uint32_t dstA[4], szA[4];
#pragma unroll
    for (int q = 0; q < 4; q++) {
        int idx = tid + q * 256, row = idx >> 3, cc = idx & 7;
        int f = row >> 4;
        int b = g_fB[ib * 8 + f];
        int r = g_fR[ib * 8 + f] + (row & 15);
        int il = (b >= 0) ? (__ldg(&im_len[b]) - 1) : 0;
        szA[q] = (b >= 0 && r < il) ? 16u : 0u;
        int bs = b < 0 ? 0 : b;
        srcA[q] = (const char*)(g_A + ((size_t)bs * AROWS + r) * DDIM) + cc * 16;
        dstA[q] = sbase + row * PITCH + cc * 16;
    }
    const char* srcB[5]; uint32_t dstB[5], szB[5];
#pragma unroll
    for (int q = 0; q < 5; q++) {
        int idx = tid + q * 256, row = idx >> 3, cc = idx & 7;
        int blk = row >> 3;
        int j = g_bJ[jb * NCAP + blk];
        int w = g_bW[jb * NCAP + blk] + (row & 7);
        int sl = (j >= 0) ? (__ldg(&s_len[j]) - 3) : 0;
        szB[q] = (j >= 0 && w < sl) ? 16u : 0u;
        int js = j < 0 ? 0 : j;
        srcB[q] = (const char*)(g_S + ((size_t)js * SROWS + w) * DDIM) + cc * 16;
        dstB[q] = sbase + ASTAGE + row * PITCH + cc * 16;
    }

    // ldmatrix lane addresses
    const int quad = lane >> 3, r8 = lane & 7;
    const uint32_t a_lane = (uint32_t)((wm * 32 + (quad & 1) * 8 + r8) * PITCH
                                       + (quad >> 1) * 16);
    const uint32_t b_lane = (uint32_t)(ASTAGE
                                       + (wn * 80 + (quad >> 1) * 8 + r8) * PITCH
                                       + (quad & 1) * 16);

    float c[2][10][4];
#pragma unroll
    for (int mt = 0; mt < 2; mt++)
#pragma unroll
        for (int nt = 0; nt < 10; nt++)
#pragma unroll
            for (int q = 0; q < 4; q++) c[mt][nt][q] = 0.0f;

    // ---- prologue: stage 0 in flight ----
#pragma unroll
    for (int q = 0; q < 4; q++) CP_ASYNC16Z(dstA[q], srcA[q], szA[q]);
#pragma unroll
    for (int q = 0; q < 5; q++) CP_ASYNC16Z(dstB[q], srcB[q], szB[q]);
    CP_COMMIT();

#pragma unroll 1
    for (int kt = 0; kt < 16; kt++) {
        CP_WAIT0();            // kt's loads done (single group outstanding)
        __syncthreads();       // visible to all; stage (kt-1)&1 = (kt+1)&1 now free

        if (kt + 1 < 16) {     // prefetch kt+1 into the freed stage; overlaps compute
            uint32_t so = (uint32_t)(((kt + 1) & 1) * STAGE_SZ);
            uint32_t ko = (uint32_t)((kt + 1) * 128);
#pragma unroll
            for (int q = 0; q < 4; q++) CP_ASYNC16Z(dstA[q] + so, srcA[q] + ko, szA[q]);
#pragma unroll
            for (int q = 0; q < 5; q++) CP_ASYNC16Z(dstB[q] + so, srcB[q] + ko, szB[q]);
            CP_COMMIT();
        }

        const uint32_t stga = sbase + (uint32_t)((kt & 1) * STAGE_SZ);
#pragma unroll
        for (int step = 0; step < 4; step++) {
            uint32_t areg[2][4], breg[5][4];
#pragma unroll
            for (int mt = 0; mt < 2; mt++)
                LDSM4(areg[mt], stga + a_lane + mt * 16 * PITCH + step * 32);
#pragma unroll
            for (int nn = 0; nn < 5; nn++)
                LDSM4(breg[nn], stga + b_lane + nn * 16 * PITCH + step * 32);
#pragma unroll
            for (int mt = 0; mt < 2; mt++)
#pragma unroll
                for (int nt = 0; nt < 10; nt++)
                    MMA16816(c[mt][nt], areg[mt], breg[nt >> 1][(nt & 1) * 2],
                             breg[nt >> 1][(nt & 1) * 2 + 1]);
        }
    }
    __syncthreads();       // compute done; smem reused for C

    // ---- store C tile to smem: [128][CPITCH] floats ----
    float* C  = (float*)smem;
    float* RM = (float*)(smem + 128 * CPITCH * 4);   // [128][NCAP] row maxes
    float* CM = RM + 128 * NCAP;                     // [8][160] col maxes
#pragma unroll
    for (int mt = 0; mt < 2; mt++)
#pragma unroll
        for (int nt = 0; nt < 10; nt++) {
            int row = wm * 32 + mt * 16 + (lane >> 2);
            int col = wn * 80 + nt * 8 + (lane & 3) * 2;
            *(float2*)&C[row * CPITCH + col]       = make_float2(c[mt][nt][0], c[mt][nt][1]);
            *(float2*)&C[(row + 8) * CPITCH + col] = make_float2(c[mt][nt][2], c[mt][nt][3]);
        }
    __syncthreads();

    const int nmb = g_mN[ib], njb = g_nN[jb];

    // ---- row part: per row, per j-batch: max over w<sl (+0 iff sl<37) ----
    if (tid < 128) {
        const float* Cr = &C[tid * CPITCH];
        for (int js = 0; js < njb; js++) {
            int cs = g_nCS[jb * NCAP + js], sl = g_nSL[jb * NCAP + js];
            float m = Cr[cs];
            for (int w = 1; w < sl; w++) m = fmaxf(m, Cr[cs + w]);
            if (sl < 37) m = fmaxf(m, 0.0f);
            RM[tid * NCAP + js] = m;
        }
    }
    // ---- col part: per col, per m-batch: max over r<il (+0 iff il<49) ----
    if (tid < 160) {
        for (int ms = 0; ms < nmb; ms++) {
            int rs = g_mRS[ib * 8 + ms], il = g_mIL[ib * 8 + ms];
            float m = C[rs * CPITCH + tid];
            for (int r = 1; r < il; r++) m = fmaxf(m, C[(rs + r) * CPITCH + tid]);
            if (il < 49) m = fmaxf(m, 0.0f);
            CM[ms * 160 + tid] = m;
        }
    }
    __syncthreads();

    // ---- per-pair reduction & output ----
    if (tid < nmb * njb) {
        int ms = tid / njb, js = tid - ms * njb;
        int rs = g_mRS[ib * 8 + ms], il = g_mIL[ib * 8 + ms];
        int cs = g_nCS[jb * NCAP + js], sl = g_nSL[jb * NCAP + js];
        float sum = 0.0f;
        for (int r = 0; r < il; r++) sum += RM[(rs + r) * NCAP + js];
        for (int w = 0; w < sl; w++) sum += CM[ms * 160 + cs + w];
        out[g_mB[ib * 8 + ms] * NBATCH + g_nB[jb * NCAP + js]] = sum;
    }
}

extern "C" void kernel_launch(void* const* d_in, const int* in_sizes, int n_in,
                              void* d_out, int out_size) {
    (void)in_sizes; (void)n_in; (void)out_size;
    const float* im   = (const float*)d_in[0];
    const float* s    = (const float*)d_in[1];
    const int* im_len = (const int*)d_in[2];
    const int* s_len  = (const int*)d_in[3];
    float* out = (float*)d_out;

    conv_plan_kernel<<<6657, 256>>>(im, s, im_len, s_len);

    cudaFuncSetAttribute(align_gemm_kernel,
                         cudaFuncAttributeMaxDynamicSharedMemorySize, SMEM_BYTES);
    dim3 grid(TNMAX, 64);
    align_gemm_kernel<<<grid, 256, SMEM_BYTES>>>(im_len, s_len, out);
}

// round 16
// speedup vs baseline: 1.3544x; 1.0959x over previous
#include <cuda_runtime.h>
#include <cuda_fp16.h>
#include <cstdint>

// Problem: B=128, L_IM=50, L_S=40, D=1024
// im = im_set[:,1:,:]  -> il = im_len-1 valid rows (9..49)
// s  = s_seq[:,1:-2,:] -> sl = s_len-3  valid rows (7..37)
// Batches bin-packed (whole) into dense GEMM tiles at FINE granularity
// (independent of MMA shape -- every output row/col is independent):
//   M: ceil(il/8) 8-row fragments, 16 per 128-row tile   (<= 64 tiles)
//   N: ceil(sl/4) 4-col blocks,    40 per 160-col tile   (<= 40 tiles)
// Packing computed in closed form; pad rows/cols are exact zeros (zfill).
// GEMM: 256-thr CTAs, 2 CTAs/SM for barrier overlap.
#define NBATCH 128
#define DDIM   1024
#define AROWS  64
#define SROWS  40
#define MFRAG  16        // M fragments (8-row) per tile
#define NBLK   40        // N blocks (4-col) per tile
#define MSLOT  8         // max batches per M tile (16/2)
#define NSLOT  20        // max batches per N tile (40/2)
#define TNMAX  40

__device__ __align__(1024) __half g_A[(size_t)NBATCH * AROWS * DDIM];  // 16 MB
__device__ __align__(1024) __half g_S[(size_t)NBATCH * SROWS * DDIM];  // 10 MB

// ---- packing plan ----
__device__ int g_TM, g_TN;
__device__ int g_fB[64 * MFRAG], g_fR[64 * MFRAG];       // M fragment -> batch, row base
__device__ int g_mN[64], g_mB[64 * MSLOT], g_mRS[64 * MSLOT], g_mIL[64 * MSLOT];
__device__ int g_bJ[TNMAX * NBLK], g_bW[TNMAX * NBLK];   // N block -> batch, w base
__device__ int g_nN[TNMAX], g_nB[TNMAX * NSLOT], g_nCS[TNMAX * NSLOT], g_nSL[TNMAX * NSLOT];

// ---------------- helpers ----------------
__device__ __forceinline__ uint32_t smem_u32(const void* p) {
    uint32_t a;
    asm("{ .reg .u64 t; cvta.to.shared.u64 t, %1; cvt.u32.u64 %0, t; }" : "=r"(a) : "l"(p));
    return a;
}

#define CP_ASYNC16Z(dst, src, sz) \
    asm volatile("cp.async.cg.shared.global [%0], [%1], 16, %2;" \
                 :: "r"(dst), "l"(src), "r"(sz))
#define CP_COMMIT() asm volatile("cp.async.commit_group;" ::: "memory")
#define CP_WAIT0()  asm volatile("cp.async.wait_group 0;" ::: "memory")

#define LDSM4(r, addr) \
    asm volatile("ldmatrix.sync.aligned.m8n8.x4.shared.b16 {%0,%1,%2,%3}, [%4];" \
                 : "=r"((r)[0]), "=r"((r)[1]), "=r"((r)[2]), "=r"((r)[3]) : "r"(addr))

#define MMA16816(c, a, b0, b1) \
    asm volatile("mma.sync.aligned.m16n8k16.row.col.f32.f16.f16.f32 " \
                 "{%0,%1,%2,%3},{%4,%5,%6,%7},{%8,%9},{%0,%1,%2,%3};" \
                 : "+f"((c)[0]), "+f"((c)[1]), "+f"((c)[2]), "+f"((c)[3]) \
                 : "r"((a)[0]), "r"((a)[1]), "r"((a)[2]), "r"((a)[3]), "r"(b0), "r"(b1))

// Closed-form first-fit over classes DESCENDING, rank within class.
struct PackPos { int tile, off, slot, ntiles; };
__device__ __forceinline__ PackPos pack_pos(int myClass, int myRank,
                                            const int* cnt, int cmin, int cmax, int cap) {
    int t0 = 0, u0 = 0, s0 = 0;
    PackPos p; p.tile = 0; p.off = 0; p.slot = 0;
    for (int c = cmax; c >= cmin; c--) {
        int n  = cnt[c];
        int k0 = (cap - u0) / c;
        int kc = cap / c;
        if (c == myClass) {
            if (myRank < k0) { p.tile = t0; p.off = u0 + myRank * c; p.slot = s0 + myRank; }
            else {
                int rp = myRank - k0;
                p.tile = t0 + 1 + rp / kc;
                p.off  = (rp % kc) * c;
                p.slot = rp % kc;
            }
        }
        if (n > 0) {
            if (n <= k0) { u0 += n * c; s0 += n; }
            else {
                int rp   = n - k0;
                int full = (rp - 1) / kc;
                int last = (rp - 1) % kc + 1;
                t0 += 1 + full;
                u0 = last * c;
                s0 = last;
            }
        }
    }
    p.ntiles = t0 + 1;
    return p;
}

// ------------- merged conversion + planning -------------
// Blocks 0..6655: fp32->fp16 conversion (valid rows only). Block 6656: plan.
__global__ void conv_plan_kernel(const float* __restrict__ im, const float* __restrict__ s,
                                 const int* __restrict__ im_len, const int* __restrict__ s_len) {
    __shared__ int wcM[4][8], wcN[4][11];
    __shared__ int s_fB[64 * MFRAG], s_fR[64 * MFRAG];
    __shared__ int s_mN[64], s_mB[64 * MSLOT], s_mRS[64 * MSLOT], s_mIL[64 * MSLOT];
    __shared__ int s_bJ[TNMAX * NBLK], s_bW[TNMAX * NBLK];
    __shared__ int s_nN[TNMAX], s_nB[TNMAX * NSLOT], s_nCS[TNMAX * NSLOT], s_nSL[TNMAX * NSLOT];

    int b = blockIdx.x;
    if (b < 4096) {                                     // A path
        int u = b * 256 + threadIdx.x;
        int i  = u >> 13;
        int r  = (u >> 7) & 63;
        int d0 = (u & 127) << 3;
        int L = im_len[i] - 1;
        if (r >= L || r >= 49) return;
        const float* src = im + ((size_t)i * 50 + r + 1) * DDIM + d0;
        float4 f0 = ((const float4*)src)[0];
        float4 f1 = ((const float4*)src)[1];
        union { uint4 v; __half2 h[4]; } pk;
        pk.h[0] = __float22half2_rn(make_float2(f0.x, f0.y));
        pk.h[1] = __float22half2_rn(make_float2(f0.z, f0.w));
        pk.h[2] = __float22half2_rn(make_float2(f1.x, f1.y));
        pk.h[3] = __float22half2_rn(make_float2(f1.z, f1.w));
        *((uint4*)(g_A + ((size_t)i * AROWS + r) * DDIM + d0)) = pk.v;
    } else if (b < 6656) {                              // S path
        int u = (b - 4096) * 256 + threadIdx.x;
        int i   = u / (SROWS * 128);
        int rem = u - i * (SROWS * 128);
        int r  = rem >> 7;
        int d0 = (rem & 127) << 3;
        int L = s_len[i] - 3;
        if (r >= L || r >= 37) return;
        const float* src = s + ((size_t)i * 40 + r + 1) * DDIM + d0;
        float4 f0 = ((const float4*)src)[0];
        float4 f1 = ((const float4*)src)[1];
        union { uint4 v; __half2 h[4]; } pk;
        pk.h[0] = __float22half2_rn(make_float2(f0.x, f0.y));
        pk.h[1] = __float22half2_rn(make_float2(f0.z, f0.w));
        pk.h[2] = __float22half2_rn(make_float2(f1.x, f1.y));
        pk.h[3] = __float22half2_rn(make_float2(f1.z, f1.w));
        *((uint4*)(g_S + ((size_t)i * SROWS + r) * DDIM + d0)) = pk.v;
    } else {                                            // planning block
        const int t = threadIdx.x;
        if (t >= 128) return;
        const int w = t >> 5, ln = t & 31;
        const uint32_t lmask = (1u << ln) - 1u;

        int vI = im_len[t] - 1;  vI = vI < 1 ? 1 : (vI > 49 ? 49 : vI);
        int vS = s_len[t] - 3;   vS = vS < 1 ? 1 : (vS > 37 ? 37 : vS);
        const int frM = (vI + 7) >> 3;    // class 2..7 (8-row frags)
        const int frN = (vS + 3) >> 2;    // class 2..10 (4-col blocks)

        int rkM = 0, rkN = 0;
#pragma unroll
        for (int c = 1; c <= 7; c++) {
            uint32_t bb = __ballot_sync(0xffffffffu, frM == c);
            if (frM == c) rkM = __popc(bb & lmask);
            if (ln == 0) wcM[w][c] = __popc(bb);
        }
#pragma unroll
        for (int c = 1; c <= 10; c++) {
            uint32_t bb = __ballot_sync(0xffffffffu, frN == c);
            if (frN == c) rkN = __popc(bb & lmask);
            if (ln == 0) wcN[w][c] = __popc(bb);
        }
        for (int k = t; k < 64 * MFRAG; k += 128) { s_fB[k] = -1; s_fR[k] = 0; }
        for (int k = t; k < 64 * MSLOT; k += 128) { s_mB[k] = 0; s_mRS[k] = 0; s_mIL[k] = 1; }
        for (int k = t; k < TNMAX * NBLK; k += 128) { s_bJ[k] = -1; s_bW[k] = 0; }
        for (int k = t; k < TNMAX * NSLOT; k += 128) { s_nB[k] = 0; s_nCS[k] = 0; s_nSL[k] = 1; }
        if (t < 64) s_mN[t] = 0;
        if (t < TNMAX) s_nN[t] = 0;
        __syncthreads();

        int cntM[8], cntN[11];
#pragma unroll
        for (int c = 1; c <= 7; c++)  cntM[c] = wcM[0][c] + wcM[1][c] + wcM[2][c] + wcM[3][c];
#pragma unroll
        for (int c = 1; c <= 10; c++) cntN[c] = wcN[0][c] + wcN[1][c] + wcN[2][c] + wcN[3][c];
        for (int ww = 0; ww < 4; ww++)
            if (ww < w) { rkM += wcM[ww][frM]; rkN += wcN[ww][frN]; }

        PackPos pM = pack_pos(frM, rkM, cntM, 1, 7, MFRAG);
        PackPos pN = pack_pos(frN, rkN, cntN, 1, 10, NBLK);

        s_mB[pM.tile * MSLOT + pM.slot]  = t;
        s_mRS[pM.tile * MSLOT + pM.slot] = pM.off * 8;
        s_mIL[pM.tile * MSLOT + pM.slot] = vI;
        atomicAdd(&s_mN[pM.tile], 1);
        for (int q = 0; q < frM; q++) {
            s_fB[pM.tile * MFRAG + pM.off + q] = t;
            s_fR[pM.tile * MFRAG + pM.off + q] = q * 8;
        }
        s_nB[pN.tile * NSLOT + pN.slot]  = t;
        s_nCS[pN.tile * NSLOT + pN.slot] = pN.off * 4;
        s_nSL[pN.tile * NSLOT + pN.slot] = vS;
        atomicAdd(&s_nN[pN.tile], 1);
        for (int q = 0; q < frN; q++) {
            s_bJ[pN.tile * NBLK + pN.off + q] = t;
            s_bW[pN.tile * NBLK + pN.off + q] = q * 4;
        }
        __syncthreads();

        for (int k = t; k < 64 * MFRAG; k += 128) { g_fB[k] = s_fB[k]; g_fR[k] = s_fR[k]; }
        for (int k = t; k < 64 * MSLOT; k += 128)
            { g_mB[k] = s_mB[k]; g_mRS[k] = s_mRS[k]; g_mIL[k] = s_mIL[k]; }
        for (int k = t; k < TNMAX * NBLK; k += 128) { g_bJ[k] = s_bJ[k]; g_bW[k] = s_bW[k]; }
        for (int k = t; k < TNMAX * NSLOT; k += 128)
            { g_nB[k] = s_nB[k]; g_nCS[k] = s_nCS[k]; g_nSL[k] = s_nSL[k]; }
        if (t < 64) g_mN[t] = s_mN[t];
        if (t < TNMAX) g_nN[t] = s_nN[t];
        if (t == 0) { g_TM = pM.ntiles; g_TN = pN.ntiles; }
    }
}

// ------------- dense packed GEMM + per-pair masked max/sum epilogue -------------
// CTA: 256 threads, tile M=128 x N=160, K=1024 in 16 chunks of 64.
// Warp grid 4(m) x 2(n): warp tile 32 x 80. 2 stages, 1 barrier per kt.
// 2 CTAs/SM: independent CTAs fill each other's barrier/CP_WAIT bubbles.
#define PITCH     144
#define ASTAGE    18432              // 128*144
#define STAGE_SZ  41472              // ASTAGE + 160*144
#define CPITCH    166                // even; 166*4 % 128 = 24 -> conflict-free rows
#define SMEM_BYTES 100352            // C (84992) + RM (10240) + CM (5120)

__global__ void __launch_bounds__(256, 2) align_gemm_kernel(
        const int* __restrict__ im_len, const int* __restrict__ s_len,
        float* __restrict__ out) {
    const int jb = blockIdx.x;       // N tile (0..TNMAX-1)
    const int ib = blockIdx.y;       // M tile (0..63)
    if (ib >= g_TM || jb >= g_TN) return;

    extern __shared__ __align__(16) char smem[];
    const int tid  = threadIdx.x;
    const int lane = tid & 31;
    const int wid  = tid >> 5;
    const int wm   = wid & 3;        // M offset wm*32
    const int wn   = wid >> 2;       // N offset wn*80 (0..1)
    const uint32_t sbase = smem_u32(smem);

    // ---- per-thread load setup (advance src by 128B per kt) ----
    const char* srcA[4]; uint32_t dstA[4], szA[4];
#pragma unroll
    for (int q = 0; q < 4; q++) {
        int idx = tid + q * 256, row = idx >> 3, cc = idx & 7;
        int f = row >> 3;                     // 8-row fragment
        int b = g_fB[ib * MFRAG + f];
        int r = g_fR[ib * MFRAG + f] + (row & 7);
        int il = (b >= 0) ? (__ldg(&im_len[b]) - 1) : 0;
        szA[q] = (b >= 0 && r < il) ? 16u : 0u;
        int bs = b < 0 ? 0 : b;
        srcA[q] = (const char*)(g_A + ((size_t)bs * AROWS + r) * DDIM) + cc * 16;
        dstA[q] = sbase + row * PITCH + cc * 16;
    }
    const char* srcB[5]; uint32_t dstB[5], szB[5];
#pragma unroll
    for (int q = 0; q < 5; q++) {
        int idx = tid + q * 256, row = idx >> 3, cc = idx & 7;
        int blk = row >> 2;                   // 4-col block
        int j = g_bJ[jb * NBLK + blk];
        int w = g_bW[jb * NBLK + blk] + (row & 3);
        int sl = (j >= 0) ? (__ldg(&s_len[j]) - 3) : 0;
        szB[q] = (j >= 0 && w < sl) ? 16u : 0u;
        int js = j < 0 ? 0 : j;
        srcB[q] = (const char*)(g_S + ((size_t)js * SROWS + w) * DDIM) + cc * 16;
        dstB[q] = sbase + ASTAGE + row * PITCH + cc * 16;
    }

    // ldmatrix lane addresses
    const int quad = lane >> 3, r8 = lane & 7;
    const uint32_t a_lane = (uint32_t)((wm * 32 + (quad & 1) * 8 + r8) * PITCH
                                       + (quad >> 1) * 16);
    const uint32_t b_lane = (uint32_t)(ASTAGE
                                       + (wn * 80 + (quad >> 1) * 8 + r8) * PITCH
                                       + (quad & 1) * 16);

    float c[2][10][4];
#pragma unroll
    for (int mt = 0; mt < 2; mt++)
#pragma unroll
        for (int nt = 0; nt < 10; nt++)
#pragma unroll
            for (int q = 0; q < 4; q++) c[mt][nt][q] = 0.0f;

    // ---- prologue: stage 0 in flight ----
#pragma unroll
    for (int q = 0; q < 4; q++) CP_ASYNC16Z(dstA[q], srcA[q], szA[q]);
#pragma unroll
    for (int q = 0; q < 5; q++) CP_ASYNC16Z(dstB[q], srcB[q], szB[q]);
    CP_COMMIT();

#pragma unroll 1
    for (int kt = 0; kt < 16; kt++) {
        CP_WAIT0();            // kt's loads done (single group outstanding)
        __syncthreads();       // visible to all; stage (kt+1)&1 now free

        if (kt + 1 < 16) {     // prefetch kt+1 into the freed stage; overlaps compute
            uint32_t so = (uint32_t)(((kt + 1) & 1) * STAGE_SZ);
            uint32_t ko = (uint32_t)((kt + 1) * 128);
#pragma unroll
            for (int q = 0; q < 4; q++) CP_ASYNC16Z(dstA[q] + so, srcA[q] + ko, szA[q]);
#pragma unroll
            for (int q = 0; q < 5; q++) CP_ASYNC16Z(dstB[q] + so, srcB[q] + ko, szB[q]);
            CP_COMMIT();
        }

        const uint32_t stga = sbase + (uint32_t)((kt & 1) * STAGE_SZ);
#pragma unroll
        for (int step = 0; step < 4; step++) {
            uint32_t areg[2][4], breg[5][4];
#pragma unroll
            for (int mt = 0; mt < 2; mt++)
                LDSM4(areg[mt], stga + a_lane + mt * 16 * PITCH + step * 32);
#pragma unroll
            for (int nn = 0; nn < 5; nn++)
                LDSM4(breg[nn], stga + b_lane + nn * 16 * PITCH + step * 32);
#pragma unroll
            for (int mt = 0; mt < 2; mt++)
#pragma unroll
                for (int nt = 0; nt < 10; nt++)
                    MMA16816(c[mt][nt], areg[mt], breg[nt >> 1][(nt & 1) * 2],
                             breg[nt >> 1][(nt & 1) * 2 + 1]);
        }
    }
    __syncthreads();       // compute done; smem reused for C

    // ---- store C tile to smem: [128][CPITCH] floats ----
    float* C  = (float*)smem;
    float* RM = (float*)(smem + 128 * CPITCH * 4);   // [128][NSLOT] row maxes
    float* CM = RM + 128 * NSLOT;                    // [MSLOT][160] col maxes
#pragma unroll
    for (int mt = 0; mt < 2; mt++)
#pragma unroll
        for (int nt = 0; nt < 10; nt++) {
            int row = wm * 32 + mt * 16 + (lane >> 2);
            int col = wn * 80 + nt * 8 + (lane & 3) * 2;
            *(float2*)&C[row * CPITCH + col]       = make_float2(c[mt][nt][0], c[mt][nt][1]);
            *(float2*)&C[(row + 8) * CPITCH + col] = make_float2(c[mt][nt][2], c[mt][nt][3]);
        }
    __syncthreads();

    const int nmb = g_mN[ib], njb = g_nN[jb];

    // ---- row part: per row, per j-batch: max over w<sl (+0 iff sl<37) ----
    if (tid < 128) {
        const float* Cr = &C[tid * CPITCH];
        for (int js = 0; js < njb; js++) {
            int cs = g_nCS[jb * NSLOT + js], sl = g_nSL[jb * NSLOT + js];
            float m = Cr[cs];
            for (int w = 1; w < sl; w++) m = fmaxf(m, Cr[cs + w]);
            if (sl < 37) m = fmaxf(m, 0.0f);
            RM[tid * NSLOT + js] = m;
        }
    }
    // ---- col part: per col, per m-batch: max over r<il (+0 iff il<49) ----
    if (tid < 160) {
        for (int ms = 0; ms < nmb; ms++) {
            int rs = g_mRS[ib * MSLOT + ms], il = g_mIL[ib * MSLOT + ms];
            float m = C[rs * CPITCH + tid];
            for (int r = 1; r < il; r++) m = fmaxf(m, C[(rs + r) * CPITCH + tid]);
            if (il < 49) m = fmaxf(m, 0.0f);
            CM[ms * 160 + tid] = m;
        }
    }
    __syncthreads();

    // ---- per-pair reduction & output ----
    if (tid < nmb * njb) {
        int ms = tid / njb, js = tid - ms * njb;
        int rs = g_mRS[ib * MSLOT + ms], il = g_mIL[ib * MSLOT + ms];
        int cs = g_nCS[jb * NSLOT + js], sl = g_nSL[jb * NSLOT + js];
        float sum = 0.0f;
        for (int r = 0; r < il; r++) sum += RM[(rs + r) * NSLOT + js];
        for (int w = 0; w < sl; w++) sum += CM[ms * 160 + cs + w];
        out[g_mB[ib * MSLOT + ms] * NBATCH + g_nB[jb * NSLOT + js]] = sum;
    }
}

extern "C" void kernel_launch(void* const* d_in, const int* in_sizes, int n_in,
                              void* d_out, int out_size) {
    (void)in_sizes; (void)n_in; (void)out_size;
    const float* im   = (const float*)d_in[0];
    const float* s    = (const float*)d_in[1];
    const int* im_len = (const int*)d_in[2];
    const int* s_len  = (const int*)d_in[3];
    float* out = (float*)d_out;

    conv_plan_kernel<<<6657, 256>>>(im, s, im_len, s_len);

    cudaFuncSetAttribute(align_gemm_kernel,
                         cudaFuncAttributeMaxDynamicSharedMemorySize, SMEM_BYTES);
    dim3 grid(TNMAX, 64);
    align_gemm_kernel<<<grid, 256, SMEM_BYTES>>>(im_len, s_len, out);
}

// round 17
// speedup vs baseline: 1.3755x; 1.0156x over previous
#include <cuda_runtime.h>
#include <cuda_fp16.h>
#include <cstdint>

// Problem: B=128, L_IM=50, L_S=40, D=1024
// im = im_set[:,1:,:]  -> il = im_len-1 valid rows (9..49)
// s  = s_seq[:,1:-2,:] -> sl = s_len-3  valid rows (7..37)
// Batches bin-packed (whole) into dense GEMM tiles at fine granularity:
//   M: ceil(il/8) 8-row fragments, 16 per 128-row tile   (<= 64 tiles)
//   N: ceil(sl/4) 4-col blocks,    40 per 160-col tile   (<= 40 tiles)
// Packing computed in closed form; pad rows/cols are exact zeros (zfill).
// GEMM: 256-thr CTAs, 2 CTAs/SM; fp16 accumulators (fp32 only in epilogue).
#define NBATCH 128
#define DDIM   1024
#define AROWS  64
#define SROWS  40
#define MFRAG  16        // M fragments (8-row) per tile
#define NBLK   40        // N blocks (4-col) per tile
#define MSLOT  8         // max batches per M tile
#define NSLOT  20        // max batches per N tile
#define TNMAX  40

__device__ __align__(1024) __half g_A[(size_t)NBATCH * AROWS * DDIM];  // 16 MB
__device__ __align__(1024) __half g_S[(size_t)NBATCH * SROWS * DDIM];  // 10 MB

// ---- packing plan ----
__device__ int g_TM, g_TN;
__device__ int g_fB[64 * MFRAG], g_fR[64 * MFRAG];       // M fragment -> batch, row base
__device__ int g_mN[64], g_mB[64 * MSLOT], g_mRS[64 * MSLOT], g_mIL[64 * MSLOT];
__device__ int g_bJ[TNMAX * NBLK], g_bW[TNMAX * NBLK];   // N block -> batch, w base
__device__ int g_nN[TNMAX], g_nB[TNMAX * NSLOT], g_nCS[TNMAX * NSLOT], g_nSL[TNMAX * NSLOT];

// ---------------- helpers ----------------
__device__ __forceinline__ uint32_t smem_u32(const void* p) {
    uint32_t a;
    asm("{ .reg .u64 t; cvta.to.shared.u64 t, %1; cvt.u32.u64 %0, t; }" : "=r"(a) : "l"(p));
    return a;
}

#define CP_ASYNC16Z(dst, src, sz) \
    asm volatile("cp.async.cg.shared.global [%0], [%1], 16, %2;" \
                 :: "r"(dst), "l"(src), "r"(sz))
#define CP_COMMIT() asm volatile("cp.async.commit_group;" ::: "memory")
#define CP_WAIT0()  asm volatile("cp.async.wait_group 0;" ::: "memory")

#define LDSM4(r, addr) \
    asm volatile("ldmatrix.sync.aligned.m8n8.x4.shared.b16 {%0,%1,%2,%3}, [%4];" \
                 : "=r"((r)[0]), "=r"((r)[1]), "=r"((r)[2]), "=r"((r)[3]) : "r"(addr))

// fp16-accumulate MMA: D,C are 2 regs (4 halves) each.
#define MMA16816H(c, a, b0, b1) \
    asm volatile("mma.sync.aligned.m16n8k16.row.col.f16.f16.f16.f16 " \
                 "{%0,%1},{%2,%3,%4,%5},{%6,%7},{%0,%1};" \
                 : "+r"((c)[0]), "+r"((c)[1]) \
                 : "r"((a)[0]), "r"((a)[1]), "r"((a)[2]), "r"((a)[3]), "r"(b0), "r"(b1))

// Closed-form first-fit over classes DESCENDING, rank within class.
struct PackPos { int tile, off, slot, ntiles; };
__device__ __forceinline__ PackPos pack_pos(int myClass, int myRank,
                                            const int* cnt, int cmin, int cmax, int cap) {
    int t0 = 0, u0 = 0, s0 = 0;
    PackPos p; p.tile = 0; p.off = 0; p.slot = 0;
    for (int c = cmax; c >= cmin; c--) {
        int n  = cnt[c];
        int k0 = (cap - u0) / c;
        int kc = cap / c;
        if (c == myClass) {
            if (myRank < k0) { p.tile = t0; p.off = u0 + myRank * c; p.slot = s0 + myRank; }
            else {
                int rp = myRank - k0;
                p.tile = t0 + 1 + rp / kc;
                p.off  = (rp % kc) * c;
                p.slot = rp % kc;
            }
        }
        if (n > 0) {
            if (n <= k0) { u0 += n * c; s0 += n; }
            else {
                int rp   = n - k0;
                int full = (rp - 1) / kc;
                int last = (rp - 1) % kc + 1;
                t0 += 1 + full;
                u0 = last * c;
                s0 = last;
            }
        }
    }
    p.ntiles = t0 + 1;
    return p;
}

// ------------- merged conversion + planning -------------
// Blocks 0..6655: fp32->fp16 conversion (valid rows only). Block 6656: plan.
__global__ void conv_plan_kernel(const float* __restrict__ im, const float* __restrict__ s,
                                 const int* __restrict__ im_len, const int* __restrict__ s_len) {
    __shared__ int wcM[4][8], wcN[4][11];
    __shared__ int s_fB[64 * MFRAG], s_fR[64 * MFRAG];
    __shared__ int s_mN[64], s_mB[64 * MSLOT], s_mRS[64 * MSLOT], s_mIL[64 * MSLOT];
    __shared__ int s_bJ[TNMAX * NBLK], s_bW[TNMAX * NBLK];
    __shared__ int s_nN[TNMAX], s_nB[TNMAX * NSLOT], s_nCS[TNMAX * NSLOT], s_nSL[TNMAX * NSLOT];

    int b = blockIdx.x;
    if (b < 4096) {                                     // A path
        int u = b * 256 + threadIdx.x;
        int i  = u >> 13;
        int r  = (u >> 7) & 63;
        int d0 = (u & 127) << 3;
        int L = im_len[i] - 1;
        if (r >= L || r >= 49) return;
        const float* src = im + ((size_t)i * 50 + r + 1) * DDIM + d0;
        float4 f0 = ((const float4*)src)[0];
        float4 f1 = ((const float4*)src)[1];
        union { uint4 v; __half2 h[4]; } pk;
        pk.h[0] = __float22half2_rn(make_float2(f0.x, f0.y));
        pk.h[1] = __float22half2_rn(make_float2(f0.z, f0.w));
        pk.h[2] = __float22half2_rn(make_float2(f1.x, f1.y));
        pk.h[3] = __float22half2_rn(make_float2(f1.z, f1.w));
        *((uint4*)(g_A + ((size_t)i * AROWS + r) * DDIM + d0)) = pk.v;
    } else if (b < 6656) {                              // S path
        int u = (b - 4096) * 256 + threadIdx.x;
        int i   = u / (SROWS * 128);
        int rem = u - i * (SROWS * 128);
        int r  = rem >> 7;
        int d0 = (rem & 127) << 3;
        int L = s_len[i] - 3;
        if (r >= L || r >= 37) return;
        const float* src = s + ((size_t)i * 40 + r + 1) * DDIM + d0;
        float4 f0 = ((const float4*)src)[0];
        float4 f1 = ((const float4*)src)[1];
        union { uint4 v; __half2 h[4]; } pk;
        pk.h[0] = __float22half2_rn(make_float2(f0.x, f0.y));
        pk.h[1] = __float22half2_rn(make_float2(f0.z, f0.w));
        pk.h[2] = __float22half2_rn(make_float2(f1.x, f1.y));
        pk.h[3] = __float22half2_rn(make_float2(f1.z, f1.w));
        *((uint4*)(g_S + ((size_t)i * SROWS + r) * DDIM + d0)) = pk.v;
    } else {                                            // planning block
        const int t = threadIdx.x;
        if (t >= 128) return;
        const int w = t >> 5, ln = t & 31;
        const uint32_t lmask = (1u << ln) - 1u;

        int vI = im_len[t] - 1;  vI = vI < 1 ? 1 : (vI > 49 ? 49 : vI);
        int vS = s_len[t] - 3;   vS = vS < 1 ? 1 : (vS > 37 ? 37 : vS);
        const int frM = (vI + 7) >> 3;    // class 2..7 (8-row frags)
        const int frN = (vS + 3) >> 2;    // class 2..10 (4-col blocks)

        int rkM = 0, rkN = 0;
#pragma unroll
        for (int c = 1; c <= 7; c++) {
            uint32_t bb = __ballot_sync(0xffffffffu, frM == c);
            if (frM == c) rkM = __popc(bb & lmask);
            if (ln == 0) wcM[w][c] = __popc(bb);
        }
#pragma unroll
        for (int c = 1; c <= 10; c++) {
            uint32_t bb = __ballot_sync(0xffffffffu, frN == c);
            if (frN == c) rkN = __popc(bb & lmask);
            if (ln == 0) wcN[w][c] = __popc(bb);
        }
        for (int k = t; k < 64 * MFRAG; k += 128) { s_fB[k] = -1; s_fR[k] = 0; }
        for (int k = t; k < 64 * MSLOT; k += 128) { s_mB[k] = 0; s_mRS[k] = 0; s_mIL[k] = 1; }
        for (int k = t; k < TNMAX * NBLK; k += 128) { s_bJ[k] = -1; s_bW[k] = 0; }
        for (int k = t; k < TNMAX * NSLOT; k += 128) { s_nB[k] = 0; s_nCS[k] = 0; s_nSL[k] = 1; }
        if (t < 64) s_mN[t] = 0;
        if (t < TNMAX) s_nN[t] = 0;
        __syncthreads();

        int cntM[8], cntN[11];
#pragma unroll
        for (int c = 1; c <= 7; c++)  cntM[c] = wcM[0][c] + wcM[1][c] + wcM[2][c] + wcM[3][c];
#pragma unroll
        for (int c = 1; c <= 10; c++) cntN[c] = wcN[0][c] + wcN[1][c] + wcN[2][c] + wcN[3][c];
        for (int ww = 0; ww < 4; ww++)
            if (ww < w) { rkM += wcM[ww][frM]; rkN += wcN[ww][frN]; }

        PackPos pM = pack_pos(frM, rkM, cntM, 1, 7, MFRAG);
        PackPos pN = pack_pos(frN, rkN, cntN, 1, 10, NBLK);

        s_mB[pM.tile * MSLOT + pM.slot]  = t;
        s_mRS[pM.tile * MSLOT + pM.slot] = pM.off * 8;
        s_mIL[pM.tile * MSLOT + pM.slot] = vI;
        atomicAdd(&s_mN[pM.tile], 1);
        for (int q = 0; q < frM; q++) {
            s_fB[pM.tile * MFRAG + pM.off + q] = t;
            s_fR[pM.tile * MFRAG + pM.off + q] = q * 8;
        }
        s_nB[pN.tile * NSLOT + pN.slot]  = t;
        s_nCS[pN.tile * NSLOT + pN.slot] = pN.off * 4;
        s_nSL[pN.tile * NSLOT + pN.slot] = vS;
        atomicAdd(&s_nN[pN.tile], 1);
        for (int q = 0; q < frN; q++) {
            s_bJ[pN.tile * NBLK + pN.off + q] = t;
            s_bW[pN.tile * NBLK + pN.off + q] = q * 4;
        }
        __syncthreads();

        for (int k = t; k < 64 * MFRAG; k += 128) { g_fB[k] = s_fB[k]; g_fR[k] = s_fR[k]; }
        for (int k = t; k < 64 * MSLOT; k += 128)
            { g_mB[k] = s_mB[k]; g_mRS[k] = s_mRS[k]; g_mIL[k] = s_mIL[k]; }
        for (int k = t; k < TNMAX * NBLK; k += 128) { g_bJ[k] = s_bJ[k]; g_bW[k] = s_bW[k]; }
        for (int k = t; k < TNMAX * NSLOT; k += 128)
            { g_nB[k] = s_nB[k]; g_nCS[k] = s_nCS[k]; g_nSL[k] = s_nSL[k]; }
        if (t < 64) g_mN[t] = s_mN[t];
        if (t < TNMAX) g_nN[t] = s_nN[t];
        if (t == 0) { g_TM = pM.ntiles; g_TN = pN.ntiles; }
    }
}

// ------------- dense packed GEMM + per-pair masked max/sum epilogue -------------
// CTA: 256 threads, tile M=128 x N=160, K=1024 in 16 chunks of 64.
// Warp grid 4(m) x 2(n): warp tile 32 x 80. 2 stages, 1 barrier per kt.
// 2 CTAs/SM. fp16 accumulators (half the acc regs; fp32 only at C store).
#define PITCH     144
#define ASTAGE    18432              // 128*144
#define STAGE_SZ  41472              // ASTAGE + 160*144
#define CPITCH    166                // even; 166*4 % 128 = 24 -> conflict-free rows
#define SMEM_BYTES 100352            // C (84992) + RM (10240) + CM (5120)

__global__ void __launch_bounds__(256, 2) align_gemm_kernel(
        const int* __restrict__ im_len, const int* __restrict__ s_len,
        float* __restrict__ out) {
    const int jb = blockIdx.x;       // N tile (0..TNMAX-1)
    const int ib = blockIdx.y;       // M tile (0..63)
    if (ib >= g_TM || jb >= g_TN) return;

    extern __shared__ __align__(16) char smem[];
    const int tid  = threadIdx.x;
    const int lane = tid & 31;
    const int wid  = tid >> 5;
    const int wm   = wid & 3;        // M offset wm*32
    const int wn   = wid >> 2;       // N offset wn*80 (0..1)
    const uint32_t sbase = smem_u32(smem);

    // ---- per-thread load setup (advance src by 128B per kt) ----
    const char* srcA[4]; uint32_t dstA[4], szA[4];
#pragma unroll
    for (int q = 0; q < 4; q++) {
        int idx = tid + q * 256, row = idx >> 3, cc = idx & 7;
        int f = row >> 3;                     // 8-row fragment
        int b = g_fB[ib * MFRAG + f];
        int r = g_fR[ib * MFRAG + f] + (row & 7);
        int il = (b >= 0) ? (__ldg(&im_len[b]) - 1) : 0;
        szA[q] = (b >= 0 && r < il) ? 16u : 0u;
        int bs = b < 0 ? 0 : b;
        srcA[q] = (const char*)(g_A + ((size_t)bs * AROWS + r) * DDIM) + cc * 16;
        dstA[q] = sbase + row * PITCH + cc * 16;
    }
    const char* srcB[5]; uint32_t dstB[5], szB[5];
#pragma unroll
    for (int q = 0; q < 5; q++) {
        int idx = tid + q * 256, row = idx >> 3, cc = idx & 7;
        int blk = row >> 2;                   // 4-col block
        int j = g_bJ[jb * NBLK + blk];
        int w = g_bW[jb * NBLK + blk] + (row & 3);
        int sl = (j >= 0) ? (__ldg(&s_len[j]) - 3) : 0;
        szB[q] = (j >= 0 && w < sl) ? 16u : 0u;
        int js = j < 0 ? 0 : j;
        srcB[q] = (const char*)(g_S + ((size_t)js * SROWS + w) * DDIM) + cc * 16;
        dstB[q] = sbase + ASTAGE + row * PITCH + cc * 16;
    }

    // ldmatrix lane addresses
    const int quad = lane >> 3, r8 = lane & 7;
    const uint32_t a_lane = (uint32_t)((wm * 32 + (quad & 1) * 8 + r8) * PITCH
                                       + (quad >> 1) * 16);
    const uint32_t b_lane = (uint32_t)(ASTAGE
                                       + (wn * 80 + (quad >> 1) * 8 + r8) * PITCH
                                       + (quad & 1) * 16);

    uint32_t hc[2][10][2];           // fp16x2 accumulators
#pragma unroll
    for (int mt = 0; mt < 2; mt++)
#pragma unroll
        for (int nt = 0; nt < 10; nt++)
            { hc[mt][nt][0] = 0u; hc[mt][nt][1] = 0u; }

    // ---- prologue: stage 0 in flight ----
#pragma unroll
    for (int q = 0; q < 4; q++) CP_ASYNC16Z(dstA[q], srcA[q], szA[q]);
#pragma unroll
    for (int q = 0; q < 5; q++) CP_ASYNC16Z(dstB[q], srcB[q], szB[q]);
    CP_COMMIT();

#pragma unroll 1
    for (int kt = 0; kt < 16; kt++) {
        CP_WAIT0();            // kt's loads done (single group outstanding)
        __syncthreads();       // visible to all; stage (kt+1)&1 now free

        if (kt + 1 < 16) {     // prefetch kt+1 into the freed stage; overlaps compute
            uint32_t so = (uint32_t)(((kt + 1) & 1) * STAGE_SZ);
            uint32_t ko = (uint32_t)((kt + 1) * 128);
#pragma unroll
            for (int q = 0; q < 4; q++) CP_ASYNC16Z(dstA[q] + so, srcA[q] + ko, szA[q]);
#pragma unroll
            for (int q = 0; q < 5; q++) CP_ASYNC16Z(dstB[q] + so, srcB[q] + ko, szB[q]);
            CP_COMMIT();
        }

        const uint32_t stga = sbase + (uint32_t)((kt & 1) * STAGE_SZ);
#pragma unroll
        for (int step = 0; step < 4; step++) {
            uint32_t areg[2][4], breg[5][4];
#pragma unroll
            for (int mt = 0; mt < 2; mt++)
                LDSM4(areg[mt], stga + a_lane + mt * 16 * PITCH + step * 32);
#pragma unroll
            for (int nn = 0; nn < 5; nn++)
                LDSM4(breg[nn], stga + b_lane + nn * 16 * PITCH + step * 32);
#pragma unroll
            for (int mt = 0; mt < 2; mt++)
#pragma unroll
                for (int nt = 0; nt < 10; nt++)
                    MMA16816H(hc[mt][nt], areg[mt], breg[nt >> 1][(nt & 1) * 2],
                              breg[nt >> 1][(nt & 1) * 2 + 1]);
        }
    }
    __syncthreads();       // compute done; smem reused for C

    // ---- store C tile to smem (fp32): [128][CPITCH] floats ----
    float* C  = (float*)smem;
    float* RM = (float*)(smem + 128 * CPITCH * 4);   // [128][NSLOT] row maxes
    float* CM = RM + 128 * NSLOT;                    // [MSLOT][160] col maxes
#pragma unroll
    for (int mt = 0; mt < 2; mt++)
#pragma unroll
        for (int nt = 0; nt < 10; nt++) {
            int row = wm * 32 + mt * 16 + (lane >> 2);
            int col = wn * 80 + nt * 8 + (lane & 3) * 2;
            float2 lo = __half22float2(*(__half2*)&hc[mt][nt][0]);  // (row,   col..col+1)
            float2 hi = __half22float2(*(__half2*)&hc[mt][nt][1]);  // (row+8, col..col+1)
            *(float2*)&C[row * CPITCH + col]       = lo;
            *(float2*)&C[(row + 8) * CPITCH + col] = hi;
        }
    __syncthreads();

    const int nmb = g_mN[ib], njb = g_nN[jb];

    // ---- row part: per row, per j-batch: max over w<sl (+0 iff sl<37) ----
    if (tid < 128) {
        const float* Cr = &C[tid * CPITCH];
        for (int js = 0; js < njb; js++) {
            int cs = g_nCS[jb * NSLOT + js], sl = g_nSL[jb * NSLOT + js];
            float m = Cr[cs];
            for (int w = 1; w < sl; w++) m = fmaxf(m, Cr[cs + w]);
            if (sl < 37) m = fmaxf(m, 0.0f);
            RM[tid * NSLOT + js] = m;
        }
    }
    // ---- col part: per col, per m-batch: max over r<il (+0 iff il<49) ----
    if (tid < 160) {
        for (int ms = 0; ms < nmb; ms++) {
            int rs = g_mRS[ib * MSLOT + ms], il = g_mIL[ib * MSLOT + ms];
            float m = C[rs * CPITCH + tid];
            for (int r = 1; r < il; r++) m = fmaxf(m, C[(rs + r) * CPITCH + tid]);
            if (il < 49) m = fmaxf(m, 0.0f);
            CM[ms * 160 + tid] = m;
        }
    }
    __syncthreads();

    // ---- per-pair reduction & output ----
    if (tid < nmb * njb) {
        int ms = tid / njb, js = tid - ms * njb;
        int rs = g_mRS[ib * MSLOT + ms], il = g_mIL[ib * MSLOT + ms];
        int cs = g_nCS[jb * NSLOT + js], sl = g_nSL[jb * NSLOT + js];
        float sum = 0.0f;
        for (int r = 0; r < il; r++) sum += RM[(rs + r) * NSLOT + js];
        for (int w = 0; w < sl; w++) sum += CM[ms * 160 + cs + w];
        out[g_mB[ib * MSLOT + ms] * NBATCH + g_nB[jb * NSLOT + js]] = sum;
    }
}

extern "C" void kernel_launch(void* const* d_in, const int* in_sizes, int n_in,
                              void* d_out, int out_size) {
    (void)in_sizes; (void)n_in; (void)out_size;
    const float* im   = (const float*)d_in[0];
    const float* s    = (const float*)d_in[1];
    const int* im_len = (const int*)d_in[2];
    const int* s_len  = (const int*)d_in[3];
    float* out = (float*)d_out;

    conv_plan_kernel<<<6657, 256>>>(im, s, im_len, s_len);

    cudaFuncSetAttribute(align_gemm_kernel,
                         cudaFuncAttributeMaxDynamicSharedMemorySize, SMEM_BYTES);
    dim3 grid(TNMAX, 64);
    align_gemm_kernel<<<grid, 256, SMEM_BYTES>>>(im_len, s_len, out);
}